// round 11
// baseline (speedup 1.0000x reference)
#include <cuda_runtime.h>
#include <cstdint>

#define DEV_INLINE __device__ __forceinline__

// =====================================================================
// Compile-time DWT matrix: coeff[c] = sum_t M[c][t] * x[t]   (84 x 64)
// =====================================================================
struct MArr { float v[84 * 64]; };

constexpr int refl(int i, int n) {
    if (i < 0) i = -i;
    if (i >= n) i = 2 * (n - 1) - i;
    return i;
}

constexpr MArr build_M() {
    const float LO[8] = { -0.010597401784997278f, 0.032883011666982945f,
                           0.030841381835986965f, -0.18703481171888114f,
                          -0.02798376941698385f,  0.6308807679295904f,
                           0.7148465705525415f,   0.23037781330885523f };
    const float HI[8] = { -0.23037781330885523f,  0.7148465705525415f,
                          -0.6308807679295904f,  -0.02798376941698385f,
                           0.18703481171888114f,  0.030841381835986965f,
                           0.032883011666982945f, -0.010597401784997278f };
    MArr m{};
    for (int t = 0; t < 64; ++t) {
        float lo1[35] = {}, hi1[35] = {};
        float lo2[21] = {}, hi2[21] = {};
        for (int i = 0; i < 35; ++i) {
            float l = 0.f, h = 0.f;
            for (int j = 0; j < 8; ++j) {
                int idx = refl(2 * i + j - 6, 64);
                float xv = (idx == t) ? 1.0f : 0.0f;
                l += xv * LO[7 - j]; h += xv * HI[7 - j];
            }
            lo1[i] = l; hi1[i] = h;
        }
        for (int i = 0; i < 21; ++i) {
            float l = 0.f, h = 0.f;
            for (int j = 0; j < 8; ++j) {
                int idx = refl(2 * i + j - 6, 35);
                l += lo1[idx] * LO[7 - j]; h += lo1[idx] * HI[7 - j];
            }
            lo2[i] = l; hi2[i] = h;
        }
        for (int i = 0; i < 14; ++i) {
            float l = 0.f, h = 0.f;
            for (int j = 0; j < 8; ++j) {
                int idx = refl(2 * i + j - 6, 21);
                l += lo2[idx] * LO[7 - j]; h += lo2[idx] * HI[7 - j];
            }
            m.v[i * 64 + t]        = l;   // lo3
            m.v[(70 + i) * 64 + t] = h;   // hi3
        }
        for (int i = 0; i < 35; ++i) m.v[(14 + i) * 64 + t] = hi1[i];
        for (int i = 0; i < 21; ++i) m.v[(49 + i) * 64 + t] = hi2[i];
    }
    return m;
}

constexpr MArr M_TBL = build_M();
__constant__ MArr c_M = M_TBL;              // uniform per-warp LDC broadcast

__device__ float g_W[64 * 4096];            // Weff[k][t*64+hw], tf32-rounded
__device__ float g_P[4 * 8192 * 64];        // split-K partials

// =====================================================================
// Kernel A: Weff[k][t*64+hw] = sum_c M[c][t] * conv_w[k][c][hw]
// grid (64 k, 4 q), 256 threads, no smem. M via constant-mem float4
// (uniform within warp -> broadcast); conv_w via coalesced LDG.
// =====================================================================
__global__ void weff_kernel(const float* __restrict__ conv_w) {
    const int k   = blockIdx.x;
    const int q   = blockIdx.y;
    const int tid = threadIdx.x;
    const int hw  = tid & 63;
    const int tg  = tid >> 6;                // 4 t's per thread

    const float* cw = conv_w + (size_t)k * 84 * 64 + hw;
    const float4* m4 = reinterpret_cast<const float4*>(
        &c_M.v[q * 16 + tg * 4]);            // stride 16 float4s per c

    float acc0 = 0.f, acc1 = 0.f, acc2 = 0.f, acc3 = 0.f;
#pragma unroll 12
    for (int c = 0; c < 84; ++c) {
        const float  v = __ldg(cw + c * 64);
        const float4 m = m4[c * 16];
        acc0 = fmaf(v, m.x, acc0);
        acc1 = fmaf(v, m.y, acc1);
        acc2 = fmaf(v, m.z, acc2);
        acc3 = fmaf(v, m.w, acc3);
    }

    const int t0 = q * 16 + tg * 4;
    float* wp = g_W + (size_t)k * 4096 + (size_t)t0 * 64 + hw;
    uint32_t r;
    asm("cvt.rna.tf32.f32 %0, %1;" : "=r"(r) : "f"(acc0)); wp[0]   = __uint_as_float(r);
    asm("cvt.rna.tf32.f32 %0, %1;" : "=r"(r) : "f"(acc1)); wp[64]  = __uint_as_float(r);
    asm("cvt.rna.tf32.f32 %0, %1;" : "=r"(r) : "f"(acc2)); wp[128] = __uint_as_float(r);
    asm("cvt.rna.tf32.f32 %0, %1;" : "=r"(r) : "f"(acc3)); wp[192] = __uint_as_float(r);
}

// =====================================================================
// Kernel B: split-K tf32 GEMM partials.
// CTA: M=64, N=64, 4 warps (2m x 2n), warp tile m32 x n32.
// KC=32 per stage, 3-stage cp.async; grid (128 m-tiles, 4 k-splits).
// =====================================================================
constexpr int KSPLIT  = 4;
constexpr int KRANGE  = 4096 / KSPLIT;       // 1024
constexpr int KC      = 32;
constexpr int NCHUNK  = KRANGE / KC;         // 32
constexpr int ROWB    = 144;                 // 32 f32 + 16B pad
constexpr int A_STG   = 64 * ROWB;           // 9216
constexpr int B_STG   = 64 * ROWB;           // 9216
constexpr int A_OFF   = 0;
constexpr int B_OFF   = 3 * A_STG;           // 27648
constexpr int SMEM_REQ = B_OFF + 3 * B_STG;  // 55296

DEV_INLINE void cp16(uint32_t daddr, const void* src) {
    asm volatile("cp.async.cg.shared.global [%0], [%1], 16;\n" :: "r"(daddr), "l"(src));
}
DEV_INLINE void ldsm_x4(uint32_t* r, uint32_t addr) {
    asm volatile("ldmatrix.sync.aligned.m8n8.x4.shared.b16 {%0,%1,%2,%3}, [%4];"
                 : "=r"(r[0]), "=r"(r[1]), "=r"(r[2]), "=r"(r[3]) : "r"(addr));
}
DEV_INLINE uint32_t f2tf32(uint32_t f) {
    uint32_t r; asm("cvt.rna.tf32.f32 %0, %1;" : "=r"(r) : "r"(f)); return r;
}

__global__ __launch_bounds__(128, 4)
void gemm_kernel(const float* __restrict__ X) {
    extern __shared__ char dsm[];
    uint32_t ab;
    asm("{ .reg .u64 t; cvta.to.shared.u64 t, %1; cvt.u32.u64 %0, t; }"
        : "=r"(ab) : "l"(dsm));

    const int tid    = threadIdx.x;           // 128
    const int lane   = tid & 31;
    const int wid    = tid >> 5;              // 0..3
    const int mbase  = (wid >> 1) * 32;
    const int nbase  = (wid & 1) * 32;
    const int mblock = blockIdx.x * 64;
    const int ky     = blockIdx.y;
    const int kgbase = ky * KRANGE;

    const int aRow = mbase + ((lane >> 3) & 1) * 8 + (lane & 7);
    const uint32_t aOff = (uint32_t)(aRow * ROWB + ((lane >> 4) & 1) * 16);
    const int bRow = nbase + ((lane >> 4) & 1) * 8 + (lane & 7);
    const uint32_t bOff = (uint32_t)(bRow * ROWB + ((lane >> 3) & 1) * 16);

    float acc[2][4][4];
#pragma unroll
    for (int a = 0; a < 2; ++a)
#pragma unroll
        for (int b = 0; b < 4; ++b)
#pragma unroll
            for (int d = 0; d < 4; ++d) acc[a][b][d] = 0.f;

    auto issue_stage = [&](int chunk, int st) {
        const int kbase = kgbase + chunk * KC;
#pragma unroll
        for (int j = 0; j < 8; ++j) {
            const int id = (j < 4) ? (tid + j * 128) : (tid + (j - 4) * 128);
            const int row = id >> 3, c16 = id & 7;
            if (j < 4)
                cp16(ab + A_OFF + st * A_STG + row * ROWB + c16 * 16,
                     X + (size_t)(mblock + row) * 4096 + kbase + c16 * 4);
            else
                cp16(ab + B_OFF + st * B_STG + row * ROWB + c16 * 16,
                     g_W + (size_t)row * 4096 + kbase + c16 * 4);
        }
    };

    issue_stage(0, 0);
    asm volatile("cp.async.commit_group;\n" ::: "memory");
    issue_stage(1, 1);
    asm volatile("cp.async.commit_group;\n" ::: "memory");

#pragma unroll 1
    for (int c = 0; c < NCHUNK; ++c) {
        const int st = c % 3;
        asm volatile("cp.async.wait_group 1;\n" ::: "memory");
        __syncthreads();

        if (c + 2 < NCHUNK) issue_stage(c + 2, (c + 2) % 3);
        asm volatile("cp.async.commit_group;\n" ::: "memory");

        const uint32_t aS = ab + A_OFF + st * A_STG + aOff;
        const uint32_t bS = ab + B_OFF + st * B_STG + bOff;

        uint32_t af[2][8], bf[2][8];
        ldsm_x4(af[0] + 0, aS);
        ldsm_x4(af[0] + 4, aS + 16 * ROWB);
        ldsm_x4(bf[0] + 0, bS);
        ldsm_x4(bf[0] + 4, bS + 16 * ROWB);

#pragma unroll
        for (int kk = 0; kk < 4; ++kk) {
            const int cur = kk & 1, nxt = cur ^ 1;
            if (kk < 3) {
                const uint32_t kadd = (uint32_t)((kk + 1) * 32);
                ldsm_x4(af[nxt] + 0, aS + kadd);
                ldsm_x4(af[nxt] + 4, aS + kadd + 16 * ROWB);
                ldsm_x4(bf[nxt] + 0, bS + kadd);
                ldsm_x4(bf[nxt] + 4, bS + kadd + 16 * ROWB);
            }
            uint32_t a[8];
#pragma unroll
            for (int i = 0; i < 8; ++i) a[i] = f2tf32(af[cur][i]);
#pragma unroll
            for (int mi = 0; mi < 2; ++mi) {
#pragma unroll
                for (int ns = 0; ns < 4; ++ns) {
                    asm volatile(
                        "mma.sync.aligned.m16n8k8.row.col.f32.tf32.tf32.f32 "
                        "{%0,%1,%2,%3}, {%4,%5,%6,%7}, {%8,%9}, {%0,%1,%2,%3};\n"
                        : "+f"(acc[mi][ns][0]), "+f"(acc[mi][ns][1]),
                          "+f"(acc[mi][ns][2]), "+f"(acc[mi][ns][3])
                        : "r"(a[mi * 4 + 0]), "r"(a[mi * 4 + 1]),
                          "r"(a[mi * 4 + 2]), "r"(a[mi * 4 + 3]),
                          "r"(bf[cur][ns * 2]), "r"(bf[cur][ns * 2 + 1]));
                }
            }
        }
    }

    // ---- write partials ----
    float* pp = g_P + ((size_t)ky * 8192 + mblock) * 64;
    const int grp = lane >> 2, qid = lane & 3;
#pragma unroll
    for (int mi = 0; mi < 2; ++mi) {
#pragma unroll
        for (int ns = 0; ns < 4; ++ns) {
            const int col = nbase + ns * 8 + qid * 2;
            const int r0  = mbase + mi * 16 + grp;
            const int r1  = r0 + 8;
            *reinterpret_cast<float2*>(pp + (size_t)r0 * 64 + col) =
                make_float2(acc[mi][ns][0], acc[mi][ns][1]);
            *reinterpret_cast<float2*>(pp + (size_t)r1 * 64 + col) =
                make_float2(acc[mi][ns][2], acc[mi][ns][3]);
        }
    }
}

// =====================================================================
// Kernel C: reduce 4 partials + bias + LeakyReLU -> out
// =====================================================================
__global__ void reduce_kernel(const float* __restrict__ bias,
                              float* __restrict__ out) {
    const int idx  = blockIdx.x * 256 + threadIdx.x;   // float4 index
    const int base = idx * 4;
    const int col  = base & 63;

    const float4 p0 = *reinterpret_cast<const float4*>(g_P + base);
    const float4 p1 = *reinterpret_cast<const float4*>(g_P + 524288 + base);
    const float4 p2 = *reinterpret_cast<const float4*>(g_P + 2 * 524288 + base);
    const float4 p3 = *reinterpret_cast<const float4*>(g_P + 3 * 524288 + base);
    const float4 bb = *reinterpret_cast<const float4*>(bias + col);

    float v0 = p0.x + p1.x + p2.x + p3.x + bb.x;
    float v1 = p0.y + p1.y + p2.y + p3.y + bb.y;
    float v2 = p0.z + p1.z + p2.z + p3.z + bb.z;
    float v3 = p0.w + p1.w + p2.w + p3.w + bb.w;
    v0 = (v0 >= 0.f) ? v0 : 0.001f * v0;
    v1 = (v1 >= 0.f) ? v1 : 0.001f * v1;
    v2 = (v2 >= 0.f) ? v2 : 0.001f * v2;
    v3 = (v3 >= 0.f) ? v3 : 0.001f * v3;

    *reinterpret_cast<float4*>(out + base) = make_float4(v0, v1, v2, v3);
}

// =====================================================================
// Launch
// =====================================================================
extern "C" void kernel_launch(void* const* d_in, const int* in_sizes, int n_in,
                              void* d_out, int out_size) {
    const float* x      = (const float*)d_in[0];   // [8192,1,64,8,8]
    const float* conv_w = (const float*)d_in[1];   // [64,84,8,8]
    const float* conv_b = (const float*)d_in[2];   // [64]
    float*       out    = (float*)d_out;           // [8192,64]

    cudaFuncSetAttribute(gemm_kernel,
                         cudaFuncAttributeMaxDynamicSharedMemorySize, SMEM_REQ);

    weff_kernel<<<dim3(64, 4), 256>>>(conv_w);
    gemm_kernel<<<dim3(128, KSPLIT), 128, SMEM_REQ>>>(x);
    reduce_kernel<<<512, 256>>>(conv_b, out);
}

// round 12
// speedup vs baseline: 1.1572x; 1.1572x over previous
#include <cuda_runtime.h>
#include <cstdint>

#define DEV_INLINE __device__ __forceinline__

// =====================================================================
// Compile-time DWT matrix, TRANSPOSED: Mt[t*84 + c] = M[c][t]   (64 x 84)
// coeff[c] = sum_t M[c][t] * x[t];  rows of M: [0,14)=lo3, [14,49)=hi1,
// [49,70)=hi2, [70,84)=hi3
// =====================================================================
struct MtArr { float v[64 * 84]; };

constexpr int refl(int i, int n) {
    if (i < 0) i = -i;
    if (i >= n) i = 2 * (n - 1) - i;
    return i;
}

constexpr MtArr build_Mt() {
    const float LO[8] = { -0.010597401784997278f, 0.032883011666982945f,
                           0.030841381835986965f, -0.18703481171888114f,
                          -0.02798376941698385f,  0.6308807679295904f,
                           0.7148465705525415f,   0.23037781330885523f };
    const float HI[8] = { -0.23037781330885523f,  0.7148465705525415f,
                          -0.6308807679295904f,  -0.02798376941698385f,
                           0.18703481171888114f,  0.030841381835986965f,
                           0.032883011666982945f, -0.010597401784997278f };
    MtArr m{};
    for (int t = 0; t < 64; ++t) {
        float lo1[35] = {}, hi1[35] = {};
        float lo2[21] = {}, hi2[21] = {};
        for (int i = 0; i < 35; ++i) {
            float l = 0.f, h = 0.f;
            for (int j = 0; j < 8; ++j) {
                int idx = refl(2 * i + j - 6, 64);
                float xv = (idx == t) ? 1.0f : 0.0f;
                l += xv * LO[7 - j]; h += xv * HI[7 - j];
            }
            lo1[i] = l; hi1[i] = h;
        }
        for (int i = 0; i < 21; ++i) {
            float l = 0.f, h = 0.f;
            for (int j = 0; j < 8; ++j) {
                int idx = refl(2 * i + j - 6, 35);
                l += lo1[idx] * LO[7 - j]; h += lo1[idx] * HI[7 - j];
            }
            lo2[i] = l; hi2[i] = h;
        }
        for (int i = 0; i < 14; ++i) {
            float l = 0.f, h = 0.f;
            for (int j = 0; j < 8; ++j) {
                int idx = refl(2 * i + j - 6, 21);
                l += lo2[idx] * LO[7 - j]; h += lo2[idx] * HI[7 - j];
            }
            m.v[t * 84 + i]        = l;   // lo3
            m.v[t * 84 + 70 + i]   = h;   // hi3
        }
        for (int i = 0; i < 35; ++i) m.v[t * 84 + 14 + i] = hi1[i];
        for (int i = 0; i < 21; ++i) m.v[t * 84 + 49 + i] = hi2[i];
    }
    return m;
}

constexpr MtArr MT_TBL = build_Mt();
__device__ const MtArr g_Mt = MT_TBL;       // global: warp-uniform LDG broadcast

__device__ float g_W[64 * 4096];            // Weff[k][t*64+hw], tf32-rounded
__device__ float g_P[4 * 8192 * 64];        // split-K partials

// =====================================================================
// Kernel A: Weff[k][t*64+hw] = sum_c Mt[t*84+c] * conv_w[k][c*64+hw]
// One thread per output element. grid (64 k, 16 t-groups) x 256 threads:
// hw = tid&63 (coalesced conv_w), t = by*4 + tid>>6 (uniform per warp).
// =====================================================================
__global__ __launch_bounds__(256)
void weff_kernel(const float* __restrict__ conv_w) {
    const int k  = blockIdx.x;
    const int t  = blockIdx.y * 4 + (threadIdx.x >> 6);
    const int hw = threadIdx.x & 63;

    const float* cw = conv_w + (size_t)k * (84 * 64) + hw;
    const float* mt = g_Mt.v + t * 84;

    float acc = 0.f;
#pragma unroll 14
    for (int c = 0; c < 84; ++c)
        acc = fmaf(__ldg(cw + c * 64), mt[c], acc);

    uint32_t r;
    asm("cvt.rna.tf32.f32 %0, %1;" : "=r"(r) : "f"(acc));
    g_W[(size_t)k * 4096 + (size_t)t * 64 + hw] = __uint_as_float(r);
}

// =====================================================================
// Kernel B: split-K tf32 GEMM partials.  (unchanged from the 54.0us build)
// CTA: M=64, N=64, 4 warps (2m x 2n), warp tile m32 x n32.
// KC=32 per stage, 3-stage cp.async; grid (128 m-tiles, 4 k-splits).
// =====================================================================
constexpr int KSPLIT  = 4;
constexpr int KRANGE  = 4096 / KSPLIT;       // 1024
constexpr int KC      = 32;
constexpr int NCHUNK  = KRANGE / KC;         // 32
constexpr int ROWB    = 144;                 // 32 f32 + 16B pad
constexpr int A_STG   = 64 * ROWB;           // 9216
constexpr int B_STG   = 64 * ROWB;           // 9216
constexpr int A_OFF   = 0;
constexpr int B_OFF   = 3 * A_STG;           // 27648
constexpr int SMEM_REQ = B_OFF + 3 * B_STG;  // 55296

DEV_INLINE void cp16(uint32_t daddr, const void* src) {
    asm volatile("cp.async.cg.shared.global [%0], [%1], 16;\n" :: "r"(daddr), "l"(src));
}
DEV_INLINE void ldsm_x4(uint32_t* r, uint32_t addr) {
    asm volatile("ldmatrix.sync.aligned.m8n8.x4.shared.b16 {%0,%1,%2,%3}, [%4];"
                 : "=r"(r[0]), "=r"(r[1]), "=r"(r[2]), "=r"(r[3]) : "r"(addr));
}
DEV_INLINE uint32_t f2tf32(uint32_t f) {
    uint32_t r; asm("cvt.rna.tf32.f32 %0, %1;" : "=r"(r) : "r"(f)); return r;
}

__global__ __launch_bounds__(128, 4)
void gemm_kernel(const float* __restrict__ X) {
    extern __shared__ char dsm[];
    uint32_t ab;
    asm("{ .reg .u64 t; cvta.to.shared.u64 t, %1; cvt.u32.u64 %0, t; }"
        : "=r"(ab) : "l"(dsm));

    const int tid    = threadIdx.x;           // 128
    const int lane   = tid & 31;
    const int wid    = tid >> 5;              // 0..3
    const int mbase  = (wid >> 1) * 32;
    const int nbase  = (wid & 1) * 32;
    const int mblock = blockIdx.x * 64;
    const int ky     = blockIdx.y;
    const int kgbase = ky * KRANGE;

    const int aRow = mbase + ((lane >> 3) & 1) * 8 + (lane & 7);
    const uint32_t aOff = (uint32_t)(aRow * ROWB + ((lane >> 4) & 1) * 16);
    const int bRow = nbase + ((lane >> 4) & 1) * 8 + (lane & 7);
    const uint32_t bOff = (uint32_t)(bRow * ROWB + ((lane >> 3) & 1) * 16);

    float acc[2][4][4];
#pragma unroll
    for (int a = 0; a < 2; ++a)
#pragma unroll
        for (int b = 0; b < 4; ++b)
#pragma unroll
            for (int d = 0; d < 4; ++d) acc[a][b][d] = 0.f;

    auto issue_stage = [&](int chunk, int st) {
        const int kbase = kgbase + chunk * KC;
#pragma unroll
        for (int j = 0; j < 8; ++j) {
            const int id = (j < 4) ? (tid + j * 128) : (tid + (j - 4) * 128);
            const int row = id >> 3, c16 = id & 7;
            if (j < 4)
                cp16(ab + A_OFF + st * A_STG + row * ROWB + c16 * 16,
                     X + (size_t)(mblock + row) * 4096 + kbase + c16 * 4);
            else
                cp16(ab + B_OFF + st * B_STG + row * ROWB + c16 * 16,
                     g_W + (size_t)row * 4096 + kbase + c16 * 4);
        }
    };

    issue_stage(0, 0);
    asm volatile("cp.async.commit_group;\n" ::: "memory");
    issue_stage(1, 1);
    asm volatile("cp.async.commit_group;\n" ::: "memory");

#pragma unroll 1
    for (int c = 0; c < NCHUNK; ++c) {
        const int st = c % 3;
        asm volatile("cp.async.wait_group 1;\n" ::: "memory");
        __syncthreads();

        if (c + 2 < NCHUNK) issue_stage(c + 2, (c + 2) % 3);
        asm volatile("cp.async.commit_group;\n" ::: "memory");

        const uint32_t aS = ab + A_OFF + st * A_STG + aOff;
        const uint32_t bS = ab + B_OFF + st * B_STG + bOff;

        uint32_t af[2][8], bf[2][8];
        ldsm_x4(af[0] + 0, aS);
        ldsm_x4(af[0] + 4, aS + 16 * ROWB);
        ldsm_x4(bf[0] + 0, bS);
        ldsm_x4(bf[0] + 4, bS + 16 * ROWB);

#pragma unroll
        for (int kk = 0; kk < 4; ++kk) {
            const int cur = kk & 1, nxt = cur ^ 1;
            if (kk < 3) {
                const uint32_t kadd = (uint32_t)((kk + 1) * 32);
                ldsm_x4(af[nxt] + 0, aS + kadd);
                ldsm_x4(af[nxt] + 4, aS + kadd + 16 * ROWB);
                ldsm_x4(bf[nxt] + 0, bS + kadd);
                ldsm_x4(bf[nxt] + 4, bS + kadd + 16 * ROWB);
            }
            uint32_t a[8];
#pragma unroll
            for (int i = 0; i < 8; ++i) a[i] = f2tf32(af[cur][i]);
#pragma unroll
            for (int mi = 0; mi < 2; ++mi) {
#pragma unroll
                for (int ns = 0; ns < 4; ++ns) {
                    asm volatile(
                        "mma.sync.aligned.m16n8k8.row.col.f32.tf32.tf32.f32 "
                        "{%0,%1,%2,%3}, {%4,%5,%6,%7}, {%8,%9}, {%0,%1,%2,%3};\n"
                        : "+f"(acc[mi][ns][0]), "+f"(acc[mi][ns][1]),
                          "+f"(acc[mi][ns][2]), "+f"(acc[mi][ns][3])
                        : "r"(a[mi * 4 + 0]), "r"(a[mi * 4 + 1]),
                          "r"(a[mi * 4 + 2]), "r"(a[mi * 4 + 3]),
                          "r"(bf[cur][ns * 2]), "r"(bf[cur][ns * 2 + 1]));
                }
            }
        }
    }

    // ---- write partials ----
    float* pp = g_P + ((size_t)ky * 8192 + mblock) * 64;
    const int grp = lane >> 2, qid = lane & 3;
#pragma unroll
    for (int mi = 0; mi < 2; ++mi) {
#pragma unroll
        for (int ns = 0; ns < 4; ++ns) {
            const int col = nbase + ns * 8 + qid * 2;
            const int r0  = mbase + mi * 16 + grp;
            const int r1  = r0 + 8;
            *reinterpret_cast<float2*>(pp + (size_t)r0 * 64 + col) =
                make_float2(acc[mi][ns][0], acc[mi][ns][1]);
            *reinterpret_cast<float2*>(pp + (size_t)r1 * 64 + col) =
                make_float2(acc[mi][ns][2], acc[mi][ns][3]);
        }
    }
}

// =====================================================================
// Kernel C: reduce 4 partials + bias + LeakyReLU -> out
// =====================================================================
__global__ void reduce_kernel(const float* __restrict__ bias,
                              float* __restrict__ out) {
    const int idx  = blockIdx.x * 256 + threadIdx.x;   // float4 index
    const int base = idx * 4;
    const int col  = base & 63;

    const float4 p0 = *reinterpret_cast<const float4*>(g_P + base);
    const float4 p1 = *reinterpret_cast<const float4*>(g_P + 524288 + base);
    const float4 p2 = *reinterpret_cast<const float4*>(g_P + 2 * 524288 + base);
    const float4 p3 = *reinterpret_cast<const float4*>(g_P + 3 * 524288 + base);
    const float4 bb = *reinterpret_cast<const float4*>(bias + col);

    float v0 = p0.x + p1.x + p2.x + p3.x + bb.x;
    float v1 = p0.y + p1.y + p2.y + p3.y + bb.y;
    float v2 = p0.z + p1.z + p2.z + p3.z + bb.z;
    float v3 = p0.w + p1.w + p2.w + p3.w + bb.w;
    v0 = (v0 >= 0.f) ? v0 : 0.001f * v0;
    v1 = (v1 >= 0.f) ? v1 : 0.001f * v1;
    v2 = (v2 >= 0.f) ? v2 : 0.001f * v2;
    v3 = (v3 >= 0.f) ? v3 : 0.001f * v3;

    *reinterpret_cast<float4*>(out + base) = make_float4(v0, v1, v2, v3);
}

// =====================================================================
// Launch
// =====================================================================
extern "C" void kernel_launch(void* const* d_in, const int* in_sizes, int n_in,
                              void* d_out, int out_size) {
    const float* x      = (const float*)d_in[0];   // [8192,1,64,8,8]
    const float* conv_w = (const float*)d_in[1];   // [64,84,8,8]
    const float* conv_b = (const float*)d_in[2];   // [64]
    float*       out    = (float*)d_out;           // [8192,64]

    cudaFuncSetAttribute(gemm_kernel,
                         cudaFuncAttributeMaxDynamicSharedMemorySize, SMEM_REQ);

    weff_kernel<<<dim3(64, 16), 256>>>(conv_w);
    gemm_kernel<<<dim3(128, KSPLIT), 128, SMEM_REQ>>>(x);
    reduce_kernel<<<512, 256>>>(conv_b, out);
}